// round 16
// baseline (speedup 1.0000x reference)
#include <cuda_runtime.h>
#include <cuda_fp16.h>
#include <cstdint>

#define BB 2
#define NSEQ 2048
#define DD 256
#define HH 8
#define DH 32
#define SCALE 0.17677669529663687f  // 1/sqrt(32)

// ---------------- device scratch ----------------
__device__ float g_X[BB * NSEQ * DD];
__device__ __half g_Xh[BB * NSEQ * DD];
__device__ __half g_Oh[BB * NSEQ * DD];
__device__ __half g_Qh[BB * NSEQ * DD];
__device__ __half g_Kh[BB * NSEQ * DD];
__device__ __half g_Vh[BB * NSEQ * DD];
__device__ __half g_Eh[(size_t)BB * HH * NSEQ * NSEQ];
__device__ float g_RSI[BB * HH * NSEQ];
__device__ __half g_A0[(size_t)BB * NSEQ * NSEQ];
__device__ __half g_A1[(size_t)BB * NSEQ * NSEQ];
__device__ unsigned g_MB[NSEQ * (NSEQ / 32)];
__device__ __half g_Wqh[2 * 256 * 256];
__device__ __half g_Wkh[2 * 256 * 256];
__device__ __half g_Wvh[2 * 256 * 256];
__device__ __half g_Woh[2 * 256 * 256];
__device__ __half g_Wf0h[256 * 256];

// ---------------- asm helpers ----------------
__device__ __forceinline__ unsigned smem_u32(const void* p) {
    return (unsigned)__cvta_generic_to_shared(p);
}
__device__ __forceinline__ void cp16(unsigned dst, const void* src) {
    asm volatile("cp.async.cg.shared.global [%0], [%1], 16;" :: "r"(dst), "l"(src));
}
__device__ __forceinline__ void cp_commit() { asm volatile("cp.async.commit_group;"); }
__device__ __forceinline__ void cp_wait0() { asm volatile("cp.async.wait_group 0;" ::: "memory"); }
__device__ __forceinline__ void cp_wait1() { asm volatile("cp.async.wait_group 1;" ::: "memory"); }

__device__ __forceinline__ void ldm_x4(unsigned d[4], unsigned addr) {
    asm volatile("ldmatrix.sync.aligned.m8n8.x4.shared.b16 {%0,%1,%2,%3}, [%4];"
                 : "=r"(d[0]), "=r"(d[1]), "=r"(d[2]), "=r"(d[3]) : "r"(addr));
}
__device__ __forceinline__ void ldm_x4t(unsigned d[4], unsigned addr) {
    asm volatile("ldmatrix.sync.aligned.m8n8.x4.trans.shared.b16 {%0,%1,%2,%3}, [%4];"
                 : "=r"(d[0]), "=r"(d[1]), "=r"(d[2]), "=r"(d[3]) : "r"(addr));
}
__device__ __forceinline__ void mma_h(float d[4], const unsigned a[4], const unsigned b[2]) {
    asm volatile(
        "mma.sync.aligned.m16n8k16.row.col.f32.f16.f16.f32 "
        "{%0,%1,%2,%3}, {%4,%5,%6,%7}, {%8,%9}, {%0,%1,%2,%3};"
        : "+f"(d[0]), "+f"(d[1]), "+f"(d[2]), "+f"(d[3])
        : "r"(a[0]), "r"(a[1]), "r"(a[2]), "r"(a[3]), "r"(b[0]), "r"(b[1]));
}

// ---------------- multi-array float -> half (base selects case group) ----------------
__global__ void k_f2h_multi(
    const float* __restrict__ Wq, const float* __restrict__ Wk,
    const float* __restrict__ Wv, const float* __restrict__ Wo,
    const float* __restrict__ Wf0, const float* __restrict__ x,
    __half* __restrict__ Wqh, __half* __restrict__ Wkh,
    __half* __restrict__ Wvh, __half* __restrict__ Woh,
    __half* __restrict__ Wf0h, __half* __restrict__ xh, int base)
{
    const float* s;
    __half* d;
    int n4;
    switch (blockIdx.y + base) {
        case 0: s = Wq;  d = Wqh;  n4 = 2 * 65536 / 4; break;
        case 1: s = Wk;  d = Wkh;  n4 = 2 * 65536 / 4; break;
        case 2: s = Wv;  d = Wvh;  n4 = 2 * 65536 / 4; break;
        case 3: s = Wo;  d = Woh;  n4 = 2 * 65536 / 4; break;
        case 4: s = Wf0; d = Wf0h; n4 = 65536 / 4; break;
        default: s = x;  d = xh;   n4 = BB * NSEQ * DD / 4; break;
    }
    int i = blockIdx.x * blockDim.x + threadIdx.x;
    if (i >= n4) return;
    float4 v = *(const float4*)(s + i * 4);
    __half2 a = __floats2half2_rn(v.x, v.y);
    __half2 b = __floats2half2_rn(v.z, v.w);
    uint2 pk;
    pk.x = *(unsigned*)&a;
    pk.y = *(unsigned*)&b;
    *(uint2*)(d + i * 4) = pk;
}

// ---------------- adjacency -> bitmask ----------------
__global__ void k_maskbits(const float* __restrict__ adj, unsigned* __restrict__ mb) {
    int w = blockIdx.x * blockDim.x + threadIdx.x;
    if (w >= NSEQ * (NSEQ / 32)) return;
    int i = w >> 6;
    int c = w & 63;
    const float* row = adj + (size_t)i * NSEQ + c * 32;
    unsigned bits = 0;
#pragma unroll
    for (int t = 0; t < 32; t++) bits |= (row[t] > 0.0f) ? (1u << t) : 0u;
    mb[w] = bits;
}

// ---------------- fp16 tensor-core projection ----------------
#define PJ_STR 40
__global__ __launch_bounds__(256) void k_projh(
    const __half* __restrict__ Xin,
    const __half* __restrict__ W0, const __half* __restrict__ W1, const __half* __restrict__ W2,
    __half* __restrict__ H0, __half* __restrict__ H1, __half* __restrict__ H2,
    float* __restrict__ Fout)
{
    const __half* W = (blockIdx.z == 0) ? W0 : ((blockIdx.z == 1) ? W1 : W2);
    __half* Hc      = (blockIdx.z == 0) ? H0 : ((blockIdx.z == 1) ? H1 : H2);

    __shared__ __half Xs[2][128 * PJ_STR];
    __shared__ __half Ws[2][64 * PJ_STR];

    int m0 = blockIdx.x * 128, n0 = blockIdx.y * 64;
    int t = threadIdx.x, lane = t & 31, warp = t >> 5;
    int wm = warp >> 1, wn = warp & 1;
    int gid = lane >> 2, tig = lane & 3;

    int arow = (lane & 7) + ((lane >> 3) & 1) * 8;
    int acol = (lane >> 4) * 8;
    int brow = (lane & 7) + ((lane >> 4) & 1) * 8;
    int bcol = ((lane >> 3) & 1) * 8;

    float acc[2][4][4] = {};

    auto issue = [&](int buf, int k0) {
#pragma unroll
        for (int l = 0; l < 2; l++) {
            int idx = t + 256 * l;
            int r = idx >> 2, c = (idx & 3) * 8;
            cp16(smem_u32(&Xs[buf][r * PJ_STR + c]), Xin + (size_t)(m0 + r) * DD + k0 + c);
        }
        {
            int r = t >> 2, c = (t & 3) * 8;
            cp16(smem_u32(&Ws[buf][r * PJ_STR + c]), W + (size_t)(n0 + r) * DD + k0 + c);
        }
        cp_commit();
    };

    issue(0, 0);
    for (int kt = 0; kt < 8; kt++) {
        int buf = kt & 1;
        if (kt + 1 < 8) { issue(buf ^ 1, (kt + 1) * 32); cp_wait1(); }
        else cp_wait0();
        __syncthreads();

#pragma unroll
        for (int ks = 0; ks < 32; ks += 16) {
            unsigned af[2][4], bf[2][4];
#pragma unroll
            for (int im = 0; im < 2; im++)
                ldm_x4(af[im], smem_u32(&Xs[buf][(wm * 32 + im * 16 + arow) * PJ_STR + ks + acol]));
#pragma unroll
            for (int p = 0; p < 2; p++)
                ldm_x4(bf[p], smem_u32(&Ws[buf][(wn * 32 + p * 16 + brow) * PJ_STR + ks + bcol]));
#pragma unroll
            for (int im = 0; im < 2; im++) {
                mma_h(acc[im][0], af[im], &bf[0][0]);
                mma_h(acc[im][1], af[im], &bf[0][2]);
                mma_h(acc[im][2], af[im], &bf[1][0]);
                mma_h(acc[im][3], af[im], &bf[1][2]);
            }
        }
        __syncthreads();
    }

#pragma unroll
    for (int im = 0; im < 2; im++) {
        int r0 = m0 + wm * 32 + im * 16 + gid;
#pragma unroll
        for (int in = 0; in < 4; in++) {
            int c0 = n0 + wn * 32 + in * 8 + 2 * tig;
            if (Hc) {
                *(__half2*)(Hc + (size_t)r0 * DD + c0)       = __floats2half2_rn(acc[im][in][0], acc[im][in][1]);
                *(__half2*)(Hc + (size_t)(r0 + 8) * DD + c0) = __floats2half2_rn(acc[im][in][2], acc[im][in][3]);
            }
            if (Fout) {
                *(float2*)(Fout + (size_t)r0 * DD + c0)       = make_float2(acc[im][in][0], acc[im][in][1]);
                *(float2*)(Fout + (size_t)(r0 + 8) * DD + c0) = make_float2(acc[im][in][2], acc[im][in][3]);
            }
        }
    }
}

// ---------------- fused Wo-projection + residual + LayerNorm ----------------
#define PL_STR 40
__global__ __launch_bounds__(512) void k_projln(
    const __half* __restrict__ Oh, const __half* __restrict__ W,
    const float* __restrict__ Xin,
    const float* __restrict__ g, const float* __restrict__ bta,
    float* __restrict__ Xout, __half* __restrict__ Xh)
{
    __shared__ __half Xs[2][32 * PL_STR];
    __shared__ __half Ws[2][256 * PL_STR];
    __shared__ float red[32 * 16];
    __shared__ float red2[32 * 16];
    __shared__ float gb[512];
    __shared__ float stats[64];

    int m0 = blockIdx.x * 32;
    int t = threadIdx.x, lane = t & 31, warp = t >> 5;
    int wn = warp;
    int gid = lane >> 2, tig = lane & 3;

    if (t < 256) gb[t] = g[t];
    else gb[t] = bta[t - 256];

    int arow = (lane & 7) + ((lane >> 3) & 1) * 8;
    int acol = (lane >> 4) * 8;
    int brow = (lane & 7) + ((lane >> 4) & 1) * 8;
    int bcol = ((lane >> 3) & 1) * 8;

    float acc[2][2][4] = {};

    auto issue = [&](int buf, int k0) {
        if (t < 128) {
            int r = t >> 2, c = (t & 3) * 8;
            cp16(smem_u32(&Xs[buf][r * PL_STR + c]), Oh + (size_t)(m0 + r) * DD + k0 + c);
        }
#pragma unroll
        for (int l = 0; l < 2; l++) {
            int idx = t + 512 * l;
            int r = idx >> 2, c = (idx & 3) * 8;
            cp16(smem_u32(&Ws[buf][r * PL_STR + c]), W + (size_t)r * DD + k0 + c);
        }
        cp_commit();
    };

    issue(0, 0);
    for (int kt = 0; kt < 8; kt++) {
        int buf = kt & 1;
        if (kt + 1 < 8) { issue(buf ^ 1, (kt + 1) * 32); cp_wait1(); }
        else cp_wait0();
        __syncthreads();

#pragma unroll
        for (int ks = 0; ks < 32; ks += 16) {
            unsigned af[2][4], bf[4];
#pragma unroll
            for (int im = 0; im < 2; im++)
                ldm_x4(af[im], smem_u32(&Xs[buf][(im * 16 + arow) * PL_STR + ks + acol]));
            ldm_x4(bf, smem_u32(&Ws[buf][(wn * 16 + brow) * PL_STR + ks + bcol]));
#pragma unroll
            for (int im = 0; im < 2; im++) {
                mma_h(acc[im][0], af[im], &bf[0]);
                mma_h(acc[im][1], af[im], &bf[2]);
            }
        }
        __syncthreads();
    }

#pragma unroll
    for (int im = 0; im < 2; im++) {
#pragma unroll
        for (int h = 0; h < 2; h++) {
            int lr = im * 16 + gid + h * 8;
            float s = 0.f, s2 = 0.f;
#pragma unroll
            for (int in = 0; in < 2; in++) {
                int c = wn * 16 + in * 8 + 2 * tig;
                float2 xv = *(const float2*)(Xin + (size_t)(m0 + lr) * DD + c);
                acc[im][in][2 * h]     += xv.x;
                acc[im][in][2 * h + 1] += xv.y;
                float v0 = acc[im][in][2 * h], v1 = acc[im][in][2 * h + 1];
                s += v0 + v1;
                s2 += v0 * v0 + v1 * v1;
            }
            s  += __shfl_xor_sync(0xffffffffu, s, 1);
            s  += __shfl_xor_sync(0xffffffffu, s, 2);
            s2 += __shfl_xor_sync(0xffffffffu, s2, 1);
            s2 += __shfl_xor_sync(0xffffffffu, s2, 2);
            if (tig == 0) {
                red[lr * 16 + wn]  = s;
                red2[lr * 16 + wn] = s2;
            }
        }
    }
    __syncthreads();

    if (warp == 0) {
        float S = 0.f, S2 = 0.f;
#pragma unroll
        for (int w = 0; w < 16; w++) {
            S  += red[lane * 16 + w];
            S2 += red2[lane * 16 + w];
        }
        float mu = S * (1.0f / 256.0f);
        float var = S2 * (1.0f / 256.0f) - mu * mu;
        stats[lane * 2]     = mu;
        stats[lane * 2 + 1] = rsqrtf(var + 1e-5f);
    }
    __syncthreads();

#pragma unroll
    for (int im = 0; im < 2; im++) {
#pragma unroll
        for (int h = 0; h < 2; h++) {
            int lr = im * 16 + gid + h * 8;
            float mu = stats[lr * 2], rs = stats[lr * 2 + 1];
#pragma unroll
            for (int in = 0; in < 2; in++) {
                int c = wn * 16 + in * 8 + 2 * tig;
                float v0 = (acc[im][in][2 * h]     - mu) * rs * gb[c]     + gb[256 + c];
                float v1 = (acc[im][in][2 * h + 1] - mu) * rs * gb[c + 1] + gb[256 + c + 1];
                *(float2*)(Xout + (size_t)(m0 + lr) * DD + c) = make_float2(v0, v1);
                if (Xh)
                    *(__half2*)(Xh + (size_t)(m0 + lr) * DD + c) = __floats2half2_rn(v0, v1);
            }
        }
    }
}

// ---------------- scores via fp16 mma + mask + exp + rowsum -> E half ----------------
#define QS_STR 40
#define KS_STR 40
#define ES_STR 136
__global__ __launch_bounds__(256) void k_scores(
    const __half* __restrict__ Qh, const __half* __restrict__ Kh,
    const unsigned* __restrict__ mb,
    __half* __restrict__ Eh, float* __restrict__ RSI)
{
    __shared__ __half Qs[64 * QS_STR];
    __shared__ __half Ks[2][128 * KS_STR];
    __shared__ __half Es[64 * ES_STR];
    __shared__ float red[64 * 2];

    int bh = blockIdx.y, b = bh >> 3, h = bh & 7;
    int i0 = blockIdx.x * 64;
    int t = threadIdx.x, lane = t & 31, warp = t >> 5;
    int wm = warp & 3, wn = warp >> 2;
    int gid = lane >> 2, tig = lane & 3;

    {
        int row = t >> 2, c = (t & 3) * 8;
        cp16(smem_u32(&Qs[row * QS_STR + c]),
             Qh + ((size_t)(b * NSEQ + i0 + row)) * DD + h * 32 + c);
    }
    auto issueK = [&](int buf, int j0) {
#pragma unroll
        for (int l = 0; l < 2; l++) {
            int idx = t + 256 * l;
            int row = idx >> 2, c = (idx & 3) * 8;
            cp16(smem_u32(&Ks[buf][row * KS_STR + c]),
                 Kh + ((size_t)(b * NSEQ + j0 + row)) * DD + h * 32 + c);
        }
        cp_commit();
    };
    issueK(0, 0);

    int arow = wm * 16 + (lane & 7) + ((lane >> 3) & 1) * 8;
    int acol = (lane >> 4) * 8;
    unsigned aBase = smem_u32(&Qs[arow * QS_STR + acol]);
    int brow = (lane & 7) + ((lane >> 4) & 1) * 8;
    int bcol = ((lane >> 3) & 1) * 8;

    float sA = 0.f, sB = 0.f;
    int gi_a = i0 + wm * 16 + gid;
    int gi_b = gi_a + 8;
    int lrowA = wm * 16 + gid;

    for (int jc = 0; jc < 16; jc++) {
        int buf = jc & 1;
        int j0 = jc * 128;
        if (jc + 1 < 16) { issueK(buf ^ 1, (jc + 1) * 128); cp_wait1(); }
        else cp_wait0();
        __syncthreads();

        float acc[8][4] = {};
#pragma unroll
        for (int d0 = 0; d0 < 32; d0 += 16) {
            unsigned a[4];
            ldm_x4(a, aBase + d0 * 2);
#pragma unroll
            for (int p = 0; p < 4; p++) {
                unsigned bb[4];
                ldm_x4(bb, smem_u32(&Ks[buf][(wn * 64 + p * 16 + brow) * KS_STR + bcol + d0]));
                mma_h(acc[2 * p],     a, &bb[0]);
                mma_h(acc[2 * p + 1], a, &bb[2]);
            }
        }

        int wbase = (j0 + wn * 64) >> 5;
        unsigned wa0 = mb[gi_a * 64 + wbase], wa1 = mb[gi_a * 64 + wbase + 1];
        unsigned wb0 = mb[gi_b * 64 + wbase], wb1 = mb[gi_b * 64 + wbase + 1];
#pragma unroll
        for (int in = 0; in < 8; in++) {
            int col = wn * 64 + in * 8 + 2 * tig;
            unsigned wa = (in < 4) ? wa0 : wa1;
            unsigned wb = (in < 4) ? wb0 : wb1;
            int sh = (in * 8 + 2 * tig) & 31;
            float e0 = ((wa >> sh) & 1u)       ? __expf(acc[in][0] * SCALE) : 0.f;
            float e1 = ((wa >> (sh + 1)) & 1u) ? __expf(acc[in][1] * SCALE) : 0.f;
            float e2 = ((wb >> sh) & 1u)       ? __expf(acc[in][2] * SCALE) : 0.f;
            float e3 = ((wb >> (sh + 1)) & 1u) ? __expf(acc[in][3] * SCALE) : 0.f;
            sA += e0 + e1;
            sB += e2 + e3;
            *(__half2*)&Es[lrowA * ES_STR + col]       = __floats2half2_rn(e0, e1);
            *(__half2*)&Es[(lrowA + 8) * ES_STR + col] = __floats2half2_rn(e2, e3);
        }
        __syncthreads();
#pragma unroll
        for (int l = 0; l < 4; l++) {
            int id = t + 256 * l;
            int row = id >> 4, cc = (id & 15) * 8;
            uint4 v = *(uint4*)&Es[row * ES_STR + cc];
            *(uint4*)(Eh + ((size_t)bh * NSEQ + i0 + row) * NSEQ + j0 + cc) = v;
        }
        __syncthreads();
    }

    sA += __shfl_xor_sync(0xffffffffu, sA, 1);
    sA += __shfl_xor_sync(0xffffffffu, sA, 2);
    sB += __shfl_xor_sync(0xffffffffu, sB, 1);
    sB += __shfl_xor_sync(0xffffffffu, sB, 2);
    if (tig == 0) {
        red[(wm * 16 + gid) * 2 + wn]     = sA;
        red[(wm * 16 + gid + 8) * 2 + wn] = sB;
    }
    __syncthreads();
    if (t < 64)
        RSI[bh * NSEQ + i0 + t] = 1.0f / (red[t * 2] + red[t * 2 + 1]);
}

// ---------------- standalone head-averaged attention: A = (1/8) sum_h RSI*E ----------------
__global__ __launch_bounds__(256) void k_aagg(
    const __half* __restrict__ Eh, const float* __restrict__ RSI,
    __half* __restrict__ A)
{
    int idx = blockIdx.x * 256 + threadIdx.x;      // BB * NSEQ * (NSEQ/8) threads
    int j8 = idx & 255;                            // 8-half column group
    int i  = (idx >> 8) & (NSEQ - 1);
    int b  = idx >> 19;
    float acc[8] = {};
#pragma unroll
    for (int h = 0; h < HH; h++) {
        int bh = b * HH + h;
        float w = RSI[bh * NSEQ + i];
        uint4 e = *(const uint4*)(Eh + ((size_t)bh * NSEQ + i) * NSEQ + j8 * 8);
        float2 f0 = __half22float2(*(__half2*)&e.x);
        float2 f1 = __half22float2(*(__half2*)&e.y);
        float2 f2 = __half22float2(*(__half2*)&e.z);
        float2 f3 = __half22float2(*(__half2*)&e.w);
        acc[0] += w * f0.x; acc[1] += w * f0.y;
        acc[2] += w * f1.x; acc[3] += w * f1.y;
        acc[4] += w * f2.x; acc[5] += w * f2.y;
        acc[6] += w * f3.x; acc[7] += w * f3.y;
    }
    __half2 o0 = __floats2half2_rn(acc[0] * 0.125f, acc[1] * 0.125f);
    __half2 o1 = __floats2half2_rn(acc[2] * 0.125f, acc[3] * 0.125f);
    __half2 o2 = __floats2half2_rn(acc[4] * 0.125f, acc[5] * 0.125f);
    __half2 o3 = __floats2half2_rn(acc[6] * 0.125f, acc[7] * 0.125f);
    uint4 pk;
    pk.x = *(unsigned*)&o0; pk.y = *(unsigned*)&o1;
    pk.z = *(unsigned*)&o2; pk.w = *(unsigned*)&o3;
    *(uint4*)(A + ((size_t)b * NSEQ + i) * NSEQ + j8 * 8) = pk;
}

// ---------------- PV only (fp16 mma), double-buffered ----------------
#define PV_ES_STR 72
#define PV_VS_STR 264
#define PV_ES_HALFS (256 * PV_ES_STR)
#define PV_VS_HALFS (64 * PV_VS_STR)
#define PVAGG_SMEM ((2 * PV_ES_HALFS + 2 * PV_VS_HALFS) * 2 + 256 * 4)

__global__ __launch_bounds__(512) void k_pvagg(
    const __half* __restrict__ Eh, const float* __restrict__ RSI,
    const __half* __restrict__ Vh, __half* __restrict__ Oh)
{
    extern __shared__ __half smh[];
    __half* EsB = smh;
    __half* VsB = smh + 2 * PV_ES_HALFS;
    float* ws = (float*)(VsB + 2 * PV_VS_HALFS);

    int b = blockIdx.y, i0 = blockIdx.x * 32;
    int t = threadIdx.x, lane = t & 31, warp = t >> 5;
    int h = warp >> 1, s = warp & 1;
    int gid = lane >> 2, tig = lane & 3;

    if (t < 256) ws[t] = RSI[(b * HH + (t >> 5)) * NSEQ + i0 + (t & 31)];

    int arow = (lane & 7) + ((lane >> 3) & 1) * 8;
    int acol = (lane >> 4) * 8;
    int brow = (lane & 7) + ((lane >> 3) & 1) * 8;
    int bcol = (lane >> 4) * 8;
    int er0 = h * 32 + s * 16;

    auto issueEV = [&](int buf, int j0) {
        __half* Es = EsB + buf * PV_ES_HALFS;
        __half* Vs = VsB + buf * PV_VS_HALFS;
#pragma unroll
        for (int l = 0; l < 4; l++) {
            int idx = t + 512 * l;
            int row = idx >> 3, c = (idx & 7) * 8;
            int eh = row >> 5, ei = row & 31;
            cp16(smem_u32(&Es[row * PV_ES_STR + c]),
                 Eh + ((size_t)(b * HH + eh) * NSEQ + i0 + ei) * NSEQ + j0 + c);
        }
#pragma unroll
        for (int l = 0; l < 4; l++) {
            int idx = t + 512 * l;
            int row = idx >> 5, c = (idx & 31) * 8;
            cp16(smem_u32(&Vs[row * PV_VS_STR + c]),
                 Vh + ((size_t)(b * NSEQ + j0 + row)) * DD + c);
        }
        cp_commit();
    };
    issueEV(0, 0);

    float acc[4][4] = {};

    for (int jt = 0; jt < 32; jt++) {
        int buf = jt & 1;
        if (jt + 1 < 32) { issueEV(buf ^ 1, (jt + 1) * 64); cp_wait1(); }
        else cp_wait0();
        __syncthreads();

        __half* Es = EsB + buf * PV_ES_HALFS;
        __half* Vs = VsB + buf * PV_VS_HALFS;

#pragma unroll
        for (int ks = 0; ks < 64; ks += 16) {
            unsigned a[4];
            ldm_x4(a, smem_u32(&Es[(er0 + arow) * PV_ES_STR + ks + acol]));
#pragma unroll
            for (int p = 0; p < 2; p++) {
                unsigned bb[4];
                ldm_x4t(bb, smem_u32(&Vs[(ks + brow) * PV_VS_STR + h * 32 + p * 16 + bcol]));
                mma_h(acc[2 * p],     a, &bb[0]);
                mma_h(acc[2 * p + 1], a, &bb[2]);
            }
        }
        __syncthreads();
    }

    int r0 = s * 16 + gid;
    float w0 = ws[h * 32 + r0];
    float w1 = ws[h * 32 + r0 + 8];
#pragma unroll
    for (int in = 0; in < 4; in++) {
        int c0 = h * 32 + in * 8 + 2 * tig;
        size_t base = ((size_t)(b * NSEQ + i0 + r0)) * DD + c0;
        *(__half2*)(Oh + base)          = __floats2half2_rn(acc[in][0] * w0, acc[in][1] * w0);
        *(__half2*)(Oh + base + 8 * DD) = __floats2half2_rn(acc[in][2] * w1, acc[in][3] * w1);
    }
}

// ---------------- chain GEMM: 128x128 CTA tile, fp16 mma, double-buffered ----------------
#define CH_AS_STR 72
#define CH_BS_STR 136
#define CH_AS_HALFS (128 * CH_AS_STR)
#define CH_BS_HALFS (64 * CH_BS_STR)
#define CHAIN_SMEM ((2 * CH_AS_HALFS + 2 * CH_BS_HALFS) * 2)

__global__ __launch_bounds__(256, 2) void k_chain_h(
    const __half* __restrict__ A, const __half* __restrict__ B, float* __restrict__ C)
{
    extern __shared__ __half chs[];
    __half* AsB = chs;
    __half* BsB = chs + 2 * CH_AS_HALFS;

    int bb = blockIdx.z;
    const __half* Ab = A + (size_t)bb * NSEQ * NSEQ;
    const __half* Bb = B + (size_t)bb * NSEQ * NSEQ;
    float* Cb = C + (size_t)bb * NSEQ * NSEQ;

    int t = threadIdx.x, lane = t & 31, warp = t >> 5;
    int wm = warp >> 2, wn = warp & 3;
    int gid = lane >> 2, tig = lane & 3;
    int m0 = blockIdx.y * 128, n0 = blockIdx.x * 128;

    int arow = (lane & 7) + ((lane >> 3) & 1) * 8;
    int acol = (lane >> 4) * 8;
    int brow = (lane & 7) + ((lane >> 3) & 1) * 8;
    int bcol = (lane >> 4) * 8;

    float acc[4][4][4] = {};

    auto issue = [&](int buf, int k0) {
        __half* as = AsB + buf * CH_AS_HALFS;
        __half* bs = BsB + buf * CH_BS_HALFS;
#pragma unroll
        for (int l = 0; l < 4; l++) {
            int idx = t + 256 * l;
            int r = idx >> 3, c = (idx & 7) * 8;
            cp16(smem_u32(&as[r * CH_AS_STR + c]), Ab + (size_t)(m0 + r) * NSEQ + k0 + c);
        }
#pragma unroll
        for (int l = 0; l < 4; l++) {
            int idx = t + 256 * l;
            int r = idx >> 4, c = (idx & 15) * 8;
            cp16(smem_u32(&bs[r * CH_BS_STR + c]), Bb + (size_t)(k0 + r) * NSEQ + n0 + c);
        }
        cp_commit();
    };

    issue(0, 0);
    for (int kt = 0; kt < 32; kt++) {
        int buf = kt & 1;
        if (kt + 1 < 32) {
            issue(buf ^ 1, (kt + 1) * 64);
            cp_wait1();
        } else {
            cp_wait0();
        }
        __syncthreads();

        __half* as = AsB + buf * CH_AS_HALFS;
        __half* bs = BsB + buf * CH_BS_HALFS;
#pragma unroll
        for (int ks = 0; ks < 64; ks += 16) {
            unsigned af[4][4], bf[2][4];
#pragma unroll
            for (int im = 0; im < 4; im++)
                ldm_x4(af[im], smem_u32(&as[(wm * 64 + im * 16 + arow) * CH_AS_STR + ks + acol]));
#pragma unroll
            for (int p = 0; p < 2; p++)
                ldm_x4t(bf[p], smem_u32(&bs[(ks + brow) * CH_BS_STR + wn * 32 + p * 16 + bcol]));
#pragma unroll
            for (int im = 0; im < 4; im++) {
                mma_h(acc[im][0], af[im], &bf[0][0]);
                mma_h(acc[im][1], af[im], &bf[0][2]);
                mma_h(acc[im][2], af[im], &bf[1][0]);
                mma_h(acc[im][3], af[im], &bf[1][2]);
            }
        }
        __syncthreads();
    }

#pragma unroll
    for (int im = 0; im < 4; im++) {
        int r0 = m0 + wm * 64 + im * 16 + gid;
#pragma unroll
        for (int in = 0; in < 4; in++) {
            int c0 = n0 + wn * 32 + in * 8 + 2 * tig;
            *(float2*)(Cb + (size_t)r0 * NSEQ + c0)       = make_float2(acc[im][in][0], acc[im][in][1]);
            *(float2*)(Cb + (size_t)(r0 + 8) * NSEQ + c0) = make_float2(acc[im][in][2], acc[im][in][3]);
        }
    }
}

// ---------------- host ----------------
extern "C" void kernel_launch(void* const* d_in, const int* in_sizes, int n_in,
                              void* d_out, int out_size)
{
    const float* x     = (const float*)d_in[0];
    const float* adj   = (const float*)d_in[1];
    const float* Wf0   = (const float*)d_in[2];
    const float* Wq    = (const float*)d_in[3];
    const float* Wk    = (const float*)d_in[4];
    const float* Wv    = (const float*)d_in[5];
    const float* Wo    = (const float*)d_in[6];
    const float* gamma = (const float*)d_in[7];
    const float* beta  = (const float*)d_in[8];
    float* out_x    = (float*)d_out;
    float* out_attn = (float*)d_out + (size_t)BB * NSEQ * DD;

    float *X, *RSI;
    __half *Xh, *Oh, *Qh, *Kh, *Vh, *Eh, *A0, *A1;
    __half *Wqh, *Wkh, *Wvh, *Woh, *Wf0h;
    unsigned* MB;
    cudaGetSymbolAddress((void**)&X, g_X);
    cudaGetSymbolAddress((void**)&Xh, g_Xh);
    cudaGetSymbolAddress((void**)&Oh, g_Oh);
    cudaGetSymbolAddress((void**)&Qh, g_Qh);
    cudaGetSymbolAddress((void**)&Kh, g_Kh);
    cudaGetSymbolAddress((void**)&Vh, g_Vh);
    cudaGetSymbolAddress((void**)&Eh, g_Eh);
    cudaGetSymbolAddress((void**)&RSI, g_RSI);
    cudaGetSymbolAddress((void**)&A0, g_A0);
    cudaGetSymbolAddress((void**)&A1, g_A1);
    cudaGetSymbolAddress((void**)&MB, g_MB);
    cudaGetSymbolAddress((void**)&Wqh, g_Wqh);
    cudaGetSymbolAddress((void**)&Wkh, g_Wkh);
    cudaGetSymbolAddress((void**)&Wvh, g_Wvh);
    cudaGetSymbolAddress((void**)&Woh, g_Woh);
    cudaGetSymbolAddress((void**)&Wf0h, g_Wf0h);

    cudaFuncSetAttribute(k_pvagg, cudaFuncAttributeMaxDynamicSharedMemorySize, PVAGG_SMEM);
    cudaFuncSetAttribute(k_chain_h, cudaFuncAttributeMaxDynamicSharedMemorySize, CHAIN_SMEM);

    // side-stream + events (created fresh each call; never destroyed — see R12 note)
    cudaStream_t s2;
    cudaEvent_t evRoot, evSide, evJoin;
    cudaEvent_t evX[2], evV[2], evS[2];
    cudaStreamCreateWithFlags(&s2, cudaStreamNonBlocking);
    cudaEventCreateWithFlags(&evRoot, cudaEventDisableTiming);
    cudaEventCreateWithFlags(&evSide, cudaEventDisableTiming);
    cudaEventCreateWithFlags(&evJoin, cudaEventDisableTiming);
    for (int i = 0; i < 2; i++) {
        cudaEventCreateWithFlags(&evX[i], cudaEventDisableTiming);
        cudaEventCreateWithFlags(&evV[i], cudaEventDisableTiming);
        cudaEventCreateWithFlags(&evS[i], cudaEventDisableTiming);
    }

    const int WSZ = 256 * 256;

    // side stream: maskbits + attention-weight conversions
    cudaEventRecord(evRoot, 0);
    cudaStreamWaitEvent(s2, evRoot, 0);
    k_maskbits<<<512, 256, 0, s2>>>(adj, MB);
    k_f2h_multi<<<dim3(1024, 4), 256, 0, s2>>>(Wq, Wk, Wv, Wo, Wf0, x,
                                               Wqh, Wkh, Wvh, Woh, Wf0h, Qh, 0);
    cudaEventRecord(evSide, s2);

    // main stream: convert Wf0 + x, then f0 projection
    k_f2h_multi<<<dim3(1024, 2), 256>>>(Wq, Wk, Wv, Wo, Wf0, x,
                                        Wqh, Wkh, Wvh, Woh, Wf0h, Qh, 4);
    k_projh<<<dim3(32, 4, 1), 256>>>(Qh, Wf0h, Wf0h, Wf0h, Xh, Xh, Xh, X);

    cudaStreamWaitEvent(0, evSide, 0);

    for (int i = 0; i < 2; i++) {
        // fork V projection onto s2 (Xh ready)
        cudaEventRecord(evX[i], 0);
        cudaStreamWaitEvent(s2, evX[i], 0);
        k_projh<<<dim3(32, 4, 1), 256, 0, s2>>>(Xh, Wvh + i * WSZ, Wvh + i * WSZ, Wvh + i * WSZ,
                                                Vh, Vh, Vh, (float*)nullptr);
        cudaEventRecord(evV[i], s2);

        // QK projections + scores on main
        k_projh<<<dim3(32, 4, 2), 256>>>(Xh, Wqh + i * WSZ, Wkh + i * WSZ, Wkh + i * WSZ,
                                         Qh, Kh, Kh, (float*)nullptr);
        k_scores<<<dim3(NSEQ / 64, BB * HH), 256>>>(Qh, Kh, MB, Eh, RSI);
        cudaEventRecord(evS[i], 0);

        // head-averaged A on s2 (needs only Eh + RSI), concurrent with pvagg
        cudaStreamWaitEvent(s2, evS[i], 0);
        k_aagg<<<BB * NSEQ * (NSEQ / 8) / 256, 256, 0, s2>>>(Eh, RSI, (i == 0) ? A0 : A1);

        // PV on main
        cudaStreamWaitEvent(0, evV[i], 0);
        k_pvagg<<<dim3(NSEQ / 32, BB), 512, PVAGG_SMEM>>>(Eh, RSI, Vh, Oh);

        if (i == 1) {
            // chain on s2: in-order after aagg(1) (A1) and aagg(0) (A0)
            k_chain_h<<<dim3(NSEQ / 128, NSEQ / 128, BB), 256, CHAIN_SMEM, s2>>>(A1, A0, out_attn);
            cudaEventRecord(evJoin, s2);
        }

        if (i == 0)
            k_projln<<<BB * NSEQ / 32, 512>>>(Oh, Woh, X, gamma, beta, X, Xh);
        else
            k_projln<<<BB * NSEQ / 32, 512>>>(Oh, Woh + WSZ, X, gamma + 256, beta + 256,
                                              out_x, (__half*)nullptr);
    }

    // join chain branch back into the main stream
    cudaStreamWaitEvent(0, evJoin, 0);
}

// round 17
// speedup vs baseline: 1.0525x; 1.0525x over previous
#include <cuda_runtime.h>
#include <cuda_fp16.h>
#include <cstdint>

#define BB 2
#define NSEQ 2048
#define DD 256
#define HH 8
#define DH 32
#define SCALE 0.17677669529663687f  // 1/sqrt(32)

// ---------------- device scratch ----------------
__device__ float g_X[BB * NSEQ * DD];
__device__ __half g_Xh[BB * NSEQ * DD];
__device__ __half g_Oh[BB * NSEQ * DD];
__device__ __half g_Qh[BB * NSEQ * DD];
__device__ __half g_Kh[BB * NSEQ * DD];
__device__ __half g_Vh[BB * NSEQ * DD];
__device__ __half g_Eh[(size_t)BB * HH * NSEQ * NSEQ];
__device__ float g_RSI[BB * HH * NSEQ];
__device__ __half g_A0[(size_t)BB * NSEQ * NSEQ];
__device__ __half g_A1[(size_t)BB * NSEQ * NSEQ];
__device__ unsigned g_MB[NSEQ * (NSEQ / 32)];
__device__ __half g_Wqh[2 * 256 * 256];
__device__ __half g_Wkh[2 * 256 * 256];
__device__ __half g_Wvh[2 * 256 * 256];
__device__ __half g_Woh[2 * 256 * 256];
__device__ __half g_Wf0h[256 * 256];

// ---------------- asm helpers ----------------
__device__ __forceinline__ unsigned smem_u32(const void* p) {
    return (unsigned)__cvta_generic_to_shared(p);
}
__device__ __forceinline__ void cp16(unsigned dst, const void* src) {
    asm volatile("cp.async.cg.shared.global [%0], [%1], 16;" :: "r"(dst), "l"(src));
}
__device__ __forceinline__ void cp_commit() { asm volatile("cp.async.commit_group;"); }
__device__ __forceinline__ void cp_wait0() { asm volatile("cp.async.wait_group 0;" ::: "memory"); }
__device__ __forceinline__ void cp_wait1() { asm volatile("cp.async.wait_group 1;" ::: "memory"); }

__device__ __forceinline__ void ldm_x4(unsigned d[4], unsigned addr) {
    asm volatile("ldmatrix.sync.aligned.m8n8.x4.shared.b16 {%0,%1,%2,%3}, [%4];"
                 : "=r"(d[0]), "=r"(d[1]), "=r"(d[2]), "=r"(d[3]) : "r"(addr));
}
__device__ __forceinline__ void ldm_x4t(unsigned d[4], unsigned addr) {
    asm volatile("ldmatrix.sync.aligned.m8n8.x4.trans.shared.b16 {%0,%1,%2,%3}, [%4];"
                 : "=r"(d[0]), "=r"(d[1]), "=r"(d[2]), "=r"(d[3]) : "r"(addr));
}
__device__ __forceinline__ void mma_h(float d[4], const unsigned a[4], const unsigned b[2]) {
    asm volatile(
        "mma.sync.aligned.m16n8k16.row.col.f32.f16.f16.f32 "
        "{%0,%1,%2,%3}, {%4,%5,%6,%7}, {%8,%9}, {%0,%1,%2,%3};"
        : "+f"(d[0]), "+f"(d[1]), "+f"(d[2]), "+f"(d[3])
        : "r"(a[0]), "r"(a[1]), "r"(a[2]), "r"(a[3]), "r"(b[0]), "r"(b[1]));
}

// ---------------- multi-array float -> half (base selects case group) ----------------
__global__ void k_f2h_multi(
    const float* __restrict__ Wq, const float* __restrict__ Wk,
    const float* __restrict__ Wv, const float* __restrict__ Wo,
    const float* __restrict__ Wf0, const float* __restrict__ x,
    __half* __restrict__ Wqh, __half* __restrict__ Wkh,
    __half* __restrict__ Wvh, __half* __restrict__ Woh,
    __half* __restrict__ Wf0h, __half* __restrict__ xh, int base)
{
    const float* s;
    __half* d;
    int n4;
    switch (blockIdx.y + base) {
        case 0: s = Wq;  d = Wqh;  n4 = 2 * 65536 / 4; break;
        case 1: s = Wk;  d = Wkh;  n4 = 2 * 65536 / 4; break;
        case 2: s = Wv;  d = Wvh;  n4 = 2 * 65536 / 4; break;
        case 3: s = Wo;  d = Woh;  n4 = 2 * 65536 / 4; break;
        case 4: s = Wf0; d = Wf0h; n4 = 65536 / 4; break;
        default: s = x;  d = xh;   n4 = BB * NSEQ * DD / 4; break;
    }
    int i = blockIdx.x * blockDim.x + threadIdx.x;
    if (i >= n4) return;
    float4 v = *(const float4*)(s + i * 4);
    __half2 a = __floats2half2_rn(v.x, v.y);
    __half2 b = __floats2half2_rn(v.z, v.w);
    uint2 pk;
    pk.x = *(unsigned*)&a;
    pk.y = *(unsigned*)&b;
    *(uint2*)(d + i * 4) = pk;
}

// ---------------- adjacency -> bitmask ----------------
__global__ void k_maskbits(const float* __restrict__ adj, unsigned* __restrict__ mb) {
    int w = blockIdx.x * blockDim.x + threadIdx.x;
    if (w >= NSEQ * (NSEQ / 32)) return;
    int i = w >> 6;
    int c = w & 63;
    const float* row = adj + (size_t)i * NSEQ + c * 32;
    unsigned bits = 0;
#pragma unroll
    for (int t = 0; t < 32; t++) bits |= (row[t] > 0.0f) ? (1u << t) : 0u;
    mb[w] = bits;
}

// ---------------- fp16 tensor-core projection ----------------
#define PJ_STR 40
__global__ __launch_bounds__(256) void k_projh(
    const __half* __restrict__ Xin,
    const __half* __restrict__ W0, const __half* __restrict__ W1, const __half* __restrict__ W2,
    __half* __restrict__ H0, __half* __restrict__ H1, __half* __restrict__ H2,
    float* __restrict__ Fout)
{
    const __half* W = (blockIdx.z == 0) ? W0 : ((blockIdx.z == 1) ? W1 : W2);
    __half* Hc      = (blockIdx.z == 0) ? H0 : ((blockIdx.z == 1) ? H1 : H2);

    __shared__ __half Xs[2][128 * PJ_STR];
    __shared__ __half Ws[2][64 * PJ_STR];

    int m0 = blockIdx.x * 128, n0 = blockIdx.y * 64;
    int t = threadIdx.x, lane = t & 31, warp = t >> 5;
    int wm = warp >> 1, wn = warp & 1;
    int gid = lane >> 2, tig = lane & 3;

    int arow = (lane & 7) + ((lane >> 3) & 1) * 8;
    int acol = (lane >> 4) * 8;
    int brow = (lane & 7) + ((lane >> 4) & 1) * 8;
    int bcol = ((lane >> 3) & 1) * 8;

    float acc[2][4][4] = {};

    auto issue = [&](int buf, int k0) {
#pragma unroll
        for (int l = 0; l < 2; l++) {
            int idx = t + 256 * l;
            int r = idx >> 2, c = (idx & 3) * 8;
            cp16(smem_u32(&Xs[buf][r * PJ_STR + c]), Xin + (size_t)(m0 + r) * DD + k0 + c);
        }
        {
            int r = t >> 2, c = (t & 3) * 8;
            cp16(smem_u32(&Ws[buf][r * PJ_STR + c]), W + (size_t)(n0 + r) * DD + k0 + c);
        }
        cp_commit();
    };

    issue(0, 0);
    for (int kt = 0; kt < 8; kt++) {
        int buf = kt & 1;
        if (kt + 1 < 8) { issue(buf ^ 1, (kt + 1) * 32); cp_wait1(); }
        else cp_wait0();
        __syncthreads();

#pragma unroll
        for (int ks = 0; ks < 32; ks += 16) {
            unsigned af[2][4], bf[2][4];
#pragma unroll
            for (int im = 0; im < 2; im++)
                ldm_x4(af[im], smem_u32(&Xs[buf][(wm * 32 + im * 16 + arow) * PJ_STR + ks + acol]));
#pragma unroll
            for (int p = 0; p < 2; p++)
                ldm_x4(bf[p], smem_u32(&Ws[buf][(wn * 32 + p * 16 + brow) * PJ_STR + ks + bcol]));
#pragma unroll
            for (int im = 0; im < 2; im++) {
                mma_h(acc[im][0], af[im], &bf[0][0]);
                mma_h(acc[im][1], af[im], &bf[0][2]);
                mma_h(acc[im][2], af[im], &bf[1][0]);
                mma_h(acc[im][3], af[im], &bf[1][2]);
            }
        }
        __syncthreads();
    }

#pragma unroll
    for (int im = 0; im < 2; im++) {
        int r0 = m0 + wm * 32 + im * 16 + gid;
#pragma unroll
        for (int in = 0; in < 4; in++) {
            int c0 = n0 + wn * 32 + in * 8 + 2 * tig;
            if (Hc) {
                *(__half2*)(Hc + (size_t)r0 * DD + c0)       = __floats2half2_rn(acc[im][in][0], acc[im][in][1]);
                *(__half2*)(Hc + (size_t)(r0 + 8) * DD + c0) = __floats2half2_rn(acc[im][in][2], acc[im][in][3]);
            }
            if (Fout) {
                *(float2*)(Fout + (size_t)r0 * DD + c0)       = make_float2(acc[im][in][0], acc[im][in][1]);
                *(float2*)(Fout + (size_t)(r0 + 8) * DD + c0) = make_float2(acc[im][in][2], acc[im][in][3]);
            }
        }
    }
}

// ---------------- fused Wo-projection + residual + LayerNorm ----------------
#define PL_STR 40
__global__ __launch_bounds__(512) void k_projln(
    const __half* __restrict__ Oh, const __half* __restrict__ W,
    const float* __restrict__ Xin,
    const float* __restrict__ g, const float* __restrict__ bta,
    float* __restrict__ Xout, __half* __restrict__ Xh)
{
    __shared__ __half Xs[2][32 * PL_STR];
    __shared__ __half Ws[2][256 * PL_STR];
    __shared__ float red[32 * 16];
    __shared__ float red2[32 * 16];
    __shared__ float gb[512];
    __shared__ float stats[64];

    int m0 = blockIdx.x * 32;
    int t = threadIdx.x, lane = t & 31, warp = t >> 5;
    int wn = warp;
    int gid = lane >> 2, tig = lane & 3;

    if (t < 256) gb[t] = g[t];
    else gb[t] = bta[t - 256];

    int arow = (lane & 7) + ((lane >> 3) & 1) * 8;
    int acol = (lane >> 4) * 8;
    int brow = (lane & 7) + ((lane >> 4) & 1) * 8;
    int bcol = ((lane >> 3) & 1) * 8;

    float acc[2][2][4] = {};

    auto issue = [&](int buf, int k0) {
        if (t < 128) {
            int r = t >> 2, c = (t & 3) * 8;
            cp16(smem_u32(&Xs[buf][r * PL_STR + c]), Oh + (size_t)(m0 + r) * DD + k0 + c);
        }
#pragma unroll
        for (int l = 0; l < 2; l++) {
            int idx = t + 512 * l;
            int r = idx >> 2, c = (idx & 3) * 8;
            cp16(smem_u32(&Ws[buf][r * PL_STR + c]), W + (size_t)r * DD + k0 + c);
        }
        cp_commit();
    };

    issue(0, 0);
    for (int kt = 0; kt < 8; kt++) {
        int buf = kt & 1;
        if (kt + 1 < 8) { issue(buf ^ 1, (kt + 1) * 32); cp_wait1(); }
        else cp_wait0();
        __syncthreads();

#pragma unroll
        for (int ks = 0; ks < 32; ks += 16) {
            unsigned af[2][4], bf[4];
#pragma unroll
            for (int im = 0; im < 2; im++)
                ldm_x4(af[im], smem_u32(&Xs[buf][(im * 16 + arow) * PL_STR + ks + acol]));
            ldm_x4(bf, smem_u32(&Ws[buf][(wn * 16 + brow) * PL_STR + ks + bcol]));
#pragma unroll
            for (int im = 0; im < 2; im++) {
                mma_h(acc[im][0], af[im], &bf[0]);
                mma_h(acc[im][1], af[im], &bf[2]);
            }
        }
        __syncthreads();
    }

#pragma unroll
    for (int im = 0; im < 2; im++) {
#pragma unroll
        for (int h = 0; h < 2; h++) {
            int lr = im * 16 + gid + h * 8;
            float s = 0.f, s2 = 0.f;
#pragma unroll
            for (int in = 0; in < 2; in++) {
                int c = wn * 16 + in * 8 + 2 * tig;
                float2 xv = *(const float2*)(Xin + (size_t)(m0 + lr) * DD + c);
                acc[im][in][2 * h]     += xv.x;
                acc[im][in][2 * h + 1] += xv.y;
                float v0 = acc[im][in][2 * h], v1 = acc[im][in][2 * h + 1];
                s += v0 + v1;
                s2 += v0 * v0 + v1 * v1;
            }
            s  += __shfl_xor_sync(0xffffffffu, s, 1);
            s  += __shfl_xor_sync(0xffffffffu, s, 2);
            s2 += __shfl_xor_sync(0xffffffffu, s2, 1);
            s2 += __shfl_xor_sync(0xffffffffu, s2, 2);
            if (tig == 0) {
                red[lr * 16 + wn]  = s;
                red2[lr * 16 + wn] = s2;
            }
        }
    }
    __syncthreads();

    if (warp == 0) {
        float S = 0.f, S2 = 0.f;
#pragma unroll
        for (int w = 0; w < 16; w++) {
            S  += red[lane * 16 + w];
            S2 += red2[lane * 16 + w];
        }
        float mu = S * (1.0f / 256.0f);
        float var = S2 * (1.0f / 256.0f) - mu * mu;
        stats[lane * 2]     = mu;
        stats[lane * 2 + 1] = rsqrtf(var + 1e-5f);
    }
    __syncthreads();

#pragma unroll
    for (int im = 0; im < 2; im++) {
#pragma unroll
        for (int h = 0; h < 2; h++) {
            int lr = im * 16 + gid + h * 8;
            float mu = stats[lr * 2], rs = stats[lr * 2 + 1];
#pragma unroll
            for (int in = 0; in < 2; in++) {
                int c = wn * 16 + in * 8 + 2 * tig;
                float v0 = (acc[im][in][2 * h]     - mu) * rs * gb[c]     + gb[256 + c];
                float v1 = (acc[im][in][2 * h + 1] - mu) * rs * gb[c + 1] + gb[256 + c + 1];
                *(float2*)(Xout + (size_t)(m0 + lr) * DD + c) = make_float2(v0, v1);
                if (Xh)
                    *(__half2*)(Xh + (size_t)(m0 + lr) * DD + c) = __floats2half2_rn(v0, v1);
            }
        }
    }
}

// ---------------- scores via fp16 mma + mask + exp + rowsum -> E half ----------------
#define QS_STR 40
#define KS_STR 40
#define ES_STR 136
__global__ __launch_bounds__(256) void k_scores(
    const __half* __restrict__ Qh, const __half* __restrict__ Kh,
    const unsigned* __restrict__ mb,
    __half* __restrict__ Eh, float* __restrict__ RSI)
{
    __shared__ __half Qs[64 * QS_STR];
    __shared__ __half Ks[2][128 * KS_STR];
    __shared__ __half Es[64 * ES_STR];
    __shared__ float red[64 * 2];

    int bh = blockIdx.y, b = bh >> 3, h = bh & 7;
    int i0 = blockIdx.x * 64;
    int t = threadIdx.x, lane = t & 31, warp = t >> 5;
    int wm = warp & 3, wn = warp >> 2;
    int gid = lane >> 2, tig = lane & 3;

    {
        int row = t >> 2, c = (t & 3) * 8;
        cp16(smem_u32(&Qs[row * QS_STR + c]),
             Qh + ((size_t)(b * NSEQ + i0 + row)) * DD + h * 32 + c);
    }
    auto issueK = [&](int buf, int j0) {
#pragma unroll
        for (int l = 0; l < 2; l++) {
            int idx = t + 256 * l;
            int row = idx >> 2, c = (idx & 3) * 8;
            cp16(smem_u32(&Ks[buf][row * KS_STR + c]),
                 Kh + ((size_t)(b * NSEQ + j0 + row)) * DD + h * 32 + c);
        }
        cp_commit();
    };
    issueK(0, 0);

    int arow = wm * 16 + (lane & 7) + ((lane >> 3) & 1) * 8;
    int acol = (lane >> 4) * 8;
    unsigned aBase = smem_u32(&Qs[arow * QS_STR + acol]);
    int brow = (lane & 7) + ((lane >> 4) & 1) * 8;
    int bcol = ((lane >> 3) & 1) * 8;

    float sA = 0.f, sB = 0.f;
    int gi_a = i0 + wm * 16 + gid;
    int gi_b = gi_a + 8;
    int lrowA = wm * 16 + gid;

    for (int jc = 0; jc < 16; jc++) {
        int buf = jc & 1;
        int j0 = jc * 128;
        if (jc + 1 < 16) { issueK(buf ^ 1, (jc + 1) * 128); cp_wait1(); }
        else cp_wait0();
        __syncthreads();

        float acc[8][4] = {};
#pragma unroll
        for (int d0 = 0; d0 < 32; d0 += 16) {
            unsigned a[4];
            ldm_x4(a, aBase + d0 * 2);
#pragma unroll
            for (int p = 0; p < 4; p++) {
                unsigned bb[4];
                ldm_x4(bb, smem_u32(&Ks[buf][(wn * 64 + p * 16 + brow) * KS_STR + bcol + d0]));
                mma_h(acc[2 * p],     a, &bb[0]);
                mma_h(acc[2 * p + 1], a, &bb[2]);
            }
        }

        int wbase = (j0 + wn * 64) >> 5;
        unsigned wa0 = mb[gi_a * 64 + wbase], wa1 = mb[gi_a * 64 + wbase + 1];
        unsigned wb0 = mb[gi_b * 64 + wbase], wb1 = mb[gi_b * 64 + wbase + 1];
#pragma unroll
        for (int in = 0; in < 8; in++) {
            int col = wn * 64 + in * 8 + 2 * tig;
            unsigned wa = (in < 4) ? wa0 : wa1;
            unsigned wb = (in < 4) ? wb0 : wb1;
            int sh = (in * 8 + 2 * tig) & 31;
            float e0 = ((wa >> sh) & 1u)       ? __expf(acc[in][0] * SCALE) : 0.f;
            float e1 = ((wa >> (sh + 1)) & 1u) ? __expf(acc[in][1] * SCALE) : 0.f;
            float e2 = ((wb >> sh) & 1u)       ? __expf(acc[in][2] * SCALE) : 0.f;
            float e3 = ((wb >> (sh + 1)) & 1u) ? __expf(acc[in][3] * SCALE) : 0.f;
            sA += e0 + e1;
            sB += e2 + e3;
            *(__half2*)&Es[lrowA * ES_STR + col]       = __floats2half2_rn(e0, e1);
            *(__half2*)&Es[(lrowA + 8) * ES_STR + col] = __floats2half2_rn(e2, e3);
        }
        __syncthreads();
#pragma unroll
        for (int l = 0; l < 4; l++) {
            int id = t + 256 * l;
            int row = id >> 4, cc = (id & 15) * 8;
            uint4 v = *(uint4*)&Es[row * ES_STR + cc];
            *(uint4*)(Eh + ((size_t)bh * NSEQ + i0 + row) * NSEQ + j0 + cc) = v;
        }
        __syncthreads();
    }

    sA += __shfl_xor_sync(0xffffffffu, sA, 1);
    sA += __shfl_xor_sync(0xffffffffu, sA, 2);
    sB += __shfl_xor_sync(0xffffffffu, sB, 1);
    sB += __shfl_xor_sync(0xffffffffu, sB, 2);
    if (tig == 0) {
        red[(wm * 16 + gid) * 2 + wn]     = sA;
        red[(wm * 16 + gid + 8) * 2 + wn] = sB;
    }
    __syncthreads();
    if (t < 64)
        RSI[bh * NSEQ + i0 + t] = 1.0f / (red[t * 2] + red[t * 2 + 1]);
}

// ---------------- fused PV (fp16 mma) + head-averaged attention, double-buffered ----------------
#define PV_ES_STR 72
#define PV_VS_STR 264
#define PV_ES_HALFS (256 * PV_ES_STR)
#define PV_VS_HALFS (64 * PV_VS_STR)
#define PVAGG_SMEM ((2 * PV_ES_HALFS + 2 * PV_VS_HALFS) * 2 + 256 * 4)

__global__ __launch_bounds__(512) void k_pvagg(
    const __half* __restrict__ Eh, const float* __restrict__ RSI,
    const __half* __restrict__ Vh, __half* __restrict__ Oh, __half* __restrict__ A)
{
    extern __shared__ __half smh[];
    __half* EsB = smh;
    __half* VsB = smh + 2 * PV_ES_HALFS;
    float* ws = (float*)(VsB + 2 * PV_VS_HALFS);

    int b = blockIdx.y, i0 = blockIdx.x * 32;
    int t = threadIdx.x, lane = t & 31, warp = t >> 5;
    int h = warp >> 1, s = warp & 1;
    int gid = lane >> 2, tig = lane & 3;

    if (t < 256) ws[t] = RSI[(b * HH + (t >> 5)) * NSEQ + i0 + (t & 31)];

    int arow = (lane & 7) + ((lane >> 3) & 1) * 8;
    int acol = (lane >> 4) * 8;
    int brow = (lane & 7) + ((lane >> 3) & 1) * 8;
    int bcol = (lane >> 4) * 8;
    int er0 = h * 32 + s * 16;

    int ai = t >> 4, aj = (t & 15) * 4;

    auto issueEV = [&](int buf, int j0) {
        __half* Es = EsB + buf * PV_ES_HALFS;
        __half* Vs = VsB + buf * PV_VS_HALFS;
#pragma unroll
        for (int l = 0; l < 4; l++) {
            int idx = t + 512 * l;
            int row = idx >> 3, c = (idx & 7) * 8;
            int eh = row >> 5, ei = row & 31;
            cp16(smem_u32(&Es[row * PV_ES_STR + c]),
                 Eh + ((size_t)(b * HH + eh) * NSEQ + i0 + ei) * NSEQ + j0 + c);
        }
#pragma unroll
        for (int l = 0; l < 4; l++) {
            int idx = t + 512 * l;
            int row = idx >> 5, c = (idx & 31) * 8;
            cp16(smem_u32(&Vs[row * PV_VS_STR + c]),
                 Vh + ((size_t)(b * NSEQ + j0 + row)) * DD + c);
        }
        cp_commit();
    };
    issueEV(0, 0);

    float acc[4][4] = {};

    __syncthreads();   // ws visible to all threads before mainloop
    // hoist the 8 per-head aagg weights into registers (loop-invariant per thread)
    float wreg[8];
#pragma unroll
    for (int hh = 0; hh < 8; hh++) wreg[hh] = ws[hh * 32 + ai];

    for (int jt = 0; jt < 32; jt++) {
        int buf = jt & 1;
        int j0 = jt * 64;
        if (jt + 1 < 32) { issueEV(buf ^ 1, (jt + 1) * 64); cp_wait1(); }
        else cp_wait0();
        __syncthreads();

        __half* Es = EsB + buf * PV_ES_HALFS;
        __half* Vs = VsB + buf * PV_VS_HALFS;

        {
            float a0 = 0, a1 = 0, a2 = 0, a3 = 0;
#pragma unroll
            for (int hh = 0; hh < 8; hh++) {
                float w = wreg[hh];
                uint2 ev = *(uint2*)&Es[(hh * 32 + ai) * PV_ES_STR + aj];
                float2 f0 = __half22float2(*(__half2*)&ev.x);
                float2 f1 = __half22float2(*(__half2*)&ev.y);
                a0 += w * f0.x; a1 += w * f0.y; a2 += w * f1.x; a3 += w * f1.y;
            }
            __half2 o0 = __floats2half2_rn(a0 * 0.125f, a1 * 0.125f);
            __half2 o1 = __floats2half2_rn(a2 * 0.125f, a3 * 0.125f);
            uint2 pk;
            pk.x = *(unsigned*)&o0;
            pk.y = *(unsigned*)&o1;
            *(uint2*)(A + ((size_t)b * NSEQ + i0 + ai) * NSEQ + j0 + aj) = pk;
        }

#pragma unroll
        for (int ks = 0; ks < 64; ks += 16) {
            unsigned a[4];
            ldm_x4(a, smem_u32(&Es[(er0 + arow) * PV_ES_STR + ks + acol]));
#pragma unroll
            for (int p = 0; p < 2; p++) {
                unsigned bb[4];
                ldm_x4t(bb, smem_u32(&Vs[(ks + brow) * PV_VS_STR + h * 32 + p * 16 + bcol]));
                mma_h(acc[2 * p],     a, &bb[0]);
                mma_h(acc[2 * p + 1], a, &bb[2]);
            }
        }
        __syncthreads();
    }

    int r0 = s * 16 + gid;
    float w0 = ws[h * 32 + r0];
    float w1 = ws[h * 32 + r0 + 8];
#pragma unroll
    for (int in = 0; in < 4; in++) {
        int c0 = h * 32 + in * 8 + 2 * tig;
        size_t base = ((size_t)(b * NSEQ + i0 + r0)) * DD + c0;
        *(__half2*)(Oh + base)          = __floats2half2_rn(acc[in][0] * w0, acc[in][1] * w0);
        *(__half2*)(Oh + base + 8 * DD) = __floats2half2_rn(acc[in][2] * w1, acc[in][3] * w1);
    }
}

// ---------------- chain GEMM: 128x128 CTA tile, fp16 mma, double-buffered ----------------
#define CH_AS_STR 72
#define CH_BS_STR 136
#define CH_AS_HALFS (128 * CH_AS_STR)
#define CH_BS_HALFS (64 * CH_BS_STR)
#define CHAIN_SMEM ((2 * CH_AS_HALFS + 2 * CH_BS_HALFS) * 2)

__global__ __launch_bounds__(256, 2) void k_chain_h(
    const __half* __restrict__ A, const __half* __restrict__ B, float* __restrict__ C)
{
    extern __shared__ __half chs[];
    __half* AsB = chs;
    __half* BsB = chs + 2 * CH_AS_HALFS;

    int bb = blockIdx.z;
    const __half* Ab = A + (size_t)bb * NSEQ * NSEQ;
    const __half* Bb = B + (size_t)bb * NSEQ * NSEQ;
    float* Cb = C + (size_t)bb * NSEQ * NSEQ;

    int t = threadIdx.x, lane = t & 31, warp = t >> 5;
    int wm = warp >> 2, wn = warp & 3;
    int gid = lane >> 2, tig = lane & 3;
    int m0 = blockIdx.y * 128, n0 = blockIdx.x * 128;

    int arow = (lane & 7) + ((lane >> 3) & 1) * 8;
    int acol = (lane >> 4) * 8;
    int brow = (lane & 7) + ((lane >> 3) & 1) * 8;
    int bcol = (lane >> 4) * 8;

    float acc[4][4][4] = {};

    auto issue = [&](int buf, int k0) {
        __half* as = AsB + buf * CH_AS_HALFS;
        __half* bs = BsB + buf * CH_BS_HALFS;
#pragma unroll
        for (int l = 0; l < 4; l++) {
            int idx = t + 256 * l;
            int r = idx >> 3, c = (idx & 7) * 8;
            cp16(smem_u32(&as[r * CH_AS_STR + c]), Ab + (size_t)(m0 + r) * NSEQ + k0 + c);
        }
#pragma unroll
        for (int l = 0; l < 4; l++) {
            int idx = t + 256 * l;
            int r = idx >> 4, c = (idx & 15) * 8;
            cp16(smem_u32(&bs[r * CH_BS_STR + c]), Bb + (size_t)(k0 + r) * NSEQ + n0 + c);
        }
        cp_commit();
    };

    issue(0, 0);
    for (int kt = 0; kt < 32; kt++) {
        int buf = kt & 1;
        if (kt + 1 < 32) {
            issue(buf ^ 1, (kt + 1) * 64);
            cp_wait1();
        } else {
            cp_wait0();
        }
        __syncthreads();

        __half* as = AsB + buf * CH_AS_HALFS;
        __half* bs = BsB + buf * CH_BS_HALFS;
#pragma unroll
        for (int ks = 0; ks < 64; ks += 16) {
            unsigned af[4][4], bf[2][4];
#pragma unroll
            for (int im = 0; im < 4; im++)
                ldm_x4(af[im], smem_u32(&as[(wm * 64 + im * 16 + arow) * CH_AS_STR + ks + acol]));
#pragma unroll
            for (int p = 0; p < 2; p++)
                ldm_x4t(bf[p], smem_u32(&bs[(ks + brow) * CH_BS_STR + wn * 32 + p * 16 + bcol]));
#pragma unroll
            for (int im = 0; im < 4; im++) {
                mma_h(acc[im][0], af[im], &bf[0][0]);
                mma_h(acc[im][1], af[im], &bf[0][2]);
                mma_h(acc[im][2], af[im], &bf[1][0]);
                mma_h(acc[im][3], af[im], &bf[1][2]);
            }
        }
        __syncthreads();
    }

#pragma unroll
    for (int im = 0; im < 4; im++) {
        int r0 = m0 + wm * 64 + im * 16 + gid;
#pragma unroll
        for (int in = 0; in < 4; in++) {
            int c0 = n0 + wn * 32 + in * 8 + 2 * tig;
            *(float2*)(Cb + (size_t)r0 * NSEQ + c0)       = make_float2(acc[im][in][0], acc[im][in][1]);
            *(float2*)(Cb + (size_t)(r0 + 8) * NSEQ + c0) = make_float2(acc[im][in][2], acc[im][in][3]);
        }
    }
}

// ---------------- host ----------------
extern "C" void kernel_launch(void* const* d_in, const int* in_sizes, int n_in,
                              void* d_out, int out_size)
{
    const float* x     = (const float*)d_in[0];
    const float* adj   = (const float*)d_in[1];
    const float* Wf0   = (const float*)d_in[2];
    const float* Wq    = (const float*)d_in[3];
    const float* Wk    = (const float*)d_in[4];
    const float* Wv    = (const float*)d_in[5];
    const float* Wo    = (const float*)d_in[6];
    const float* gamma = (const float*)d_in[7];
    const float* beta  = (const float*)d_in[8];
    float* out_x    = (float*)d_out;
    float* out_attn = (float*)d_out + (size_t)BB * NSEQ * DD;

    float *X, *RSI;
    __half *Xh, *Oh, *Qh, *Kh, *Vh, *Eh, *A0, *A1;
    __half *Wqh, *Wkh, *Wvh, *Woh, *Wf0h;
    unsigned* MB;
    cudaGetSymbolAddress((void**)&X, g_X);
    cudaGetSymbolAddress((void**)&Xh, g_Xh);
    cudaGetSymbolAddress((void**)&Oh, g_Oh);
    cudaGetSymbolAddress((void**)&Qh, g_Qh);
    cudaGetSymbolAddress((void**)&Kh, g_Kh);
    cudaGetSymbolAddress((void**)&Vh, g_Vh);
    cudaGetSymbolAddress((void**)&Eh, g_Eh);
    cudaGetSymbolAddress((void**)&RSI, g_RSI);
    cudaGetSymbolAddress((void**)&A0, g_A0);
    cudaGetSymbolAddress((void**)&A1, g_A1);
    cudaGetSymbolAddress((void**)&MB, g_MB);
    cudaGetSymbolAddress((void**)&Wqh, g_Wqh);
    cudaGetSymbolAddress((void**)&Wkh, g_Wkh);
    cudaGetSymbolAddress((void**)&Wvh, g_Wvh);
    cudaGetSymbolAddress((void**)&Woh, g_Woh);
    cudaGetSymbolAddress((void**)&Wf0h, g_Wf0h);

    cudaFuncSetAttribute(k_pvagg, cudaFuncAttributeMaxDynamicSharedMemorySize, PVAGG_SMEM);
    cudaFuncSetAttribute(k_chain_h, cudaFuncAttributeMaxDynamicSharedMemorySize, CHAIN_SMEM);

    // side-stream + events (created fresh each call; never destroyed — see R12 note)
    cudaStream_t s2;
    cudaEvent_t evRoot, evSide, evFork, evJoin;
    cudaEvent_t evX[2], evV[2];
    cudaStreamCreateWithFlags(&s2, cudaStreamNonBlocking);
    cudaEventCreateWithFlags(&evRoot, cudaEventDisableTiming);
    cudaEventCreateWithFlags(&evSide, cudaEventDisableTiming);
    cudaEventCreateWithFlags(&evFork, cudaEventDisableTiming);
    cudaEventCreateWithFlags(&evJoin, cudaEventDisableTiming);
    for (int i = 0; i < 2; i++) {
        cudaEventCreateWithFlags(&evX[i], cudaEventDisableTiming);
        cudaEventCreateWithFlags(&evV[i], cudaEventDisableTiming);
    }

    const int WSZ = 256 * 256;

    // side stream: maskbits (feeds scores) + attention-weight conversions
    cudaEventRecord(evRoot, 0);
    cudaStreamWaitEvent(s2, evRoot, 0);
    k_maskbits<<<512, 256, 0, s2>>>(adj, MB);
    k_f2h_multi<<<dim3(1024, 4), 256, 0, s2>>>(Wq, Wk, Wv, Wo, Wf0, x,
                                               Wqh, Wkh, Wvh, Woh, Wf0h, Qh, 0);
    cudaEventRecord(evSide, s2);

    // main stream: convert Wf0 + x, then f0 projection
    k_f2h_multi<<<dim3(1024, 2), 256>>>(Wq, Wk, Wv, Wo, Wf0, x,
                                        Wqh, Wkh, Wvh, Woh, Wf0h, Qh, 4);
    k_projh<<<dim3(32, 4, 1), 256>>>(Qh, Wf0h, Wf0h, Wf0h, Xh, Xh, Xh, X);

    cudaStreamWaitEvent(0, evSide, 0);

    for (int i = 0; i < 2; i++) {
        // fork V projection onto s2 (Xh ready)
        cudaEventRecord(evX[i], 0);
        cudaStreamWaitEvent(s2, evX[i], 0);
        k_projh<<<dim3(32, 4, 1), 256, 0, s2>>>(Xh, Wvh + i * WSZ, Wvh + i * WSZ, Wvh + i * WSZ,
                                                Vh, Vh, Vh, (float*)nullptr);
        cudaEventRecord(evV[i], s2);

        // QK projections on main, then scores (V-proj hides under scores)
        k_projh<<<dim3(32, 4, 2), 256>>>(Xh, Wqh + i * WSZ, Wkh + i * WSZ, Wkh + i * WSZ,
                                         Qh, Kh, Kh, (float*)nullptr);
        k_scores<<<dim3(NSEQ / 64, BB * HH), 256>>>(Qh, Kh, MB, Eh, RSI);

        cudaStreamWaitEvent(0, evV[i], 0);
        k_pvagg<<<dim3(NSEQ / 32, BB), 512, PVAGG_SMEM>>>(Eh, RSI, Vh, Oh, (i == 0) ? A0 : A1);

        if (i == 1) {
            // A1 ready: fork chain onto side stream, overlapping with projln below
            cudaEventRecord(evFork, 0);
            cudaStreamWaitEvent(s2, evFork, 0);
            k_chain_h<<<dim3(NSEQ / 128, NSEQ / 128, BB), 256, CHAIN_SMEM, s2>>>(A1, A0, out_attn);
            cudaEventRecord(evJoin, s2);
        }

        if (i == 0)
            k_projln<<<BB * NSEQ / 32, 512>>>(Oh, Woh, X, gamma, beta, X, Xh);
        else
            k_projln<<<BB * NSEQ / 32, 512>>>(Oh, Woh + WSZ, X, gamma + 256, beta + 256,
                                              out_x, (__half*)nullptr);
    }

    // join chain branch back into the main stream
    cudaStreamWaitEvent(0, evJoin, 0);
}